// round 16
// baseline (speedup 1.0000x reference)
#include <cuda_runtime.h>

#define BB 16
#define TT 16

// Persistent state / intermediates (allocation-free scratch)
__device__ float g_mem1[BB * 64 * 64 * 64];
__device__ float g_mem2[BB * 128 * 32 * 32];
__device__ float g_mem3[BB * 1024];
__device__ float g_mem4[BB * 10];
__device__ float g_p1[BB * 64 * 32 * 32];   // pooled spikes layer1
__device__ float g_p2[BB * 32768];          // pooled spikes layer2 (c*256+h*16+w)
__device__ float g_s3[BB * 1024];           // spikes layer3
__device__ float g_w1T[32768 * 1024];       // fc1 weights transposed [k][o]
__device__ int   g_idx[BB * 32768];         // per-b compacted active k (ascending)
__device__ int   g_cnt[BB];

__global__ void zero_mems() {
    int i = blockIdx.x * blockDim.x + threadIdx.x;
    int stride = gridDim.x * blockDim.x;
    for (int j = i; j < BB * 64 * 64 * 64; j += stride) g_mem1[j] = 0.f;
    for (int j = i; j < BB * 128 * 32 * 32; j += stride) g_mem2[j] = 0.f;
    for (int j = i; j < BB * 1024; j += stride) g_mem3[j] = 0.f;
    for (int j = i; j < BB * 10; j += stride) g_mem4[j] = 0.f;
}

// w1 [1024][32768] -> g_w1T [32768][1024], once per call
__global__ void transpose_w1(const float* __restrict__ w) {
    __shared__ float t[32][33];
    int k0 = blockIdx.x * 32;   // k tile
    int o0 = blockIdx.y * 32;   // o tile
    int tx = threadIdx.x, ty = threadIdx.y;      // 32 x 8
#pragma unroll
    for (int dy = 0; dy < 32; dy += 8)
        t[ty + dy][tx] = w[(size_t)(o0 + ty + dy) * 32768 + k0 + tx];
    __syncthreads();
#pragma unroll
    for (int dy = 0; dy < 32; dy += 8)
        g_w1T[(size_t)(k0 + ty + dy) * 1024 + o0 + tx] = t[tx][ty + dy];
}

// ---------------------------------------------------------------------------
// conv1 (2->64, 3x3 SAME, 64x64) + LIF1 + 2x2 maxpool of spikes
// ---------------------------------------------------------------------------
__global__ __launch_bounds__(1024) void conv1_k(
    const float* __restrict__ x, const float* __restrict__ w,
    const float* __restrict__ bias, int t)
{
    __shared__ float sw[18];
    __shared__ float sb;
    int b = blockIdx.x >> 6, oc = blockIdx.x & 63;
    int tid = threadIdx.x;
    if (tid < 18) sw[tid] = w[oc * 18 + tid];
    if (tid == 0) sb = bias[oc];
    __syncthreads();

    int ph = tid >> 5, pw = tid & 31;
    int y0 = ph * 2, x0 = pw * 2;
    const float* xb = x + ((size_t)(b * TT + t)) * 2 * 4096;

    float patch[2][4][4];
#pragma unroll
    for (int ic = 0; ic < 2; ic++)
#pragma unroll
        for (int r = 0; r < 4; r++) {
            int iy = y0 - 1 + r;
#pragma unroll
            for (int c = 0; c < 4; c++) {
                int ix = x0 - 1 + c;
                patch[ic][r][c] = (iy >= 0 && iy < 64 && ix >= 0 && ix < 64)
                                  ? xb[ic * 4096 + iy * 64 + ix] : 0.f;
            }
        }

    float a00 = 0.f, a01 = 0.f, a10 = 0.f, a11 = 0.f;
#pragma unroll
    for (int ky = 0; ky < 3; ky++)
#pragma unroll
        for (int kx = 0; kx < 3; kx++)
#pragma unroll
            for (int ic = 0; ic < 2; ic++) {   // ic innermost: k = (ky,kx,ic)
                float wv = sw[ic * 9 + ky * 3 + kx];
                a00 = fmaf(patch[ic][ky][kx],         wv, a00);
                a01 = fmaf(patch[ic][ky][kx + 1],     wv, a01);
                a10 = fmaf(patch[ic][ky + 1][kx],     wv, a10);
                a11 = fmaf(patch[ic][ky + 1][kx + 1], wv, a11);
            }

    float accs[4] = {a00, a01, a10, a11};
    float smax = 0.f;
    size_t mb = ((size_t)(b * 64 + oc)) * 4096;
#pragma unroll
    for (int dy = 0; dy < 2; dy++)
#pragma unroll
        for (int dx = 0; dx < 2; dx++) {
            size_t mi = mb + (size_t)(y0 + dy) * 64 + (x0 + dx);
            float cur = __fadd_rn(accs[dy * 2 + dx], sb);
            float m = g_mem1[mi];
            float reset = (m > 1.0f) ? 1.0f : 0.0f;
            m = __fsub_rn(__fadd_rn(__fmul_rn(0.95f, m), cur), reset);
            g_mem1[mi] = m;
            if (m > 1.0f) smax = 1.f;
        }
    g_p1[((size_t)(b * 64 + oc)) * 1024 + ph * 32 + pw] = smax;
}

// ---------------------------------------------------------------------------
// conv2 (64->128, 3x3 SAME, 32x32) + LIF2 + pool, packed f32x2 FMA
// block = 256 threads = 8 rows x 32 cols, 8 ocs/thread (4 f32x2 accs).
// grid = b(16) x rowgroup(4) x ocgroup(16) = 1024 blocks.
// ---------------------------------------------------------------------------
#define FMA2(d, a, bb_, c) \
    asm("fma.rn.f32x2 %0, %1, %2, %3;" : "=l"(d) : "l"(a), "l"(bb_), "l"(c))

__global__ __launch_bounds__(256) void conv2_k(
    const float* __restrict__ w2, const float* __restrict__ b2)
{
    extern __shared__ float sm[];
    float* tile = sm;                      // [64][10][34] = 21760 floats
    float* swT  = sm + 21760;              // [9*64][8]    = 4608 floats
    float* sspk = sm + 21760 + 4608;       // [8][8][32]   = 2048 floats
    int blk = blockIdx.x;
    int ocg = blk & 15, rowg = (blk >> 4) & 3, b = blk >> 6;
    int oc0 = ocg * 8, r0 = rowg * 8;
    int tid = threadIdx.x;

    for (int i = tid; i < 21760; i += 256) {
        int ic = i / 340, rem = i - ic * 340;
        int r = rem / 34, c = rem - r * 34;
        int iy = r0 - 1 + r, ix = c - 1;
        tile[i] = (iy >= 0 && iy < 32 && ix >= 0 && ix < 32)
                  ? g_p1[((size_t)(b * 64 + ic)) * 1024 + iy * 32 + ix] : 0.f;
    }
    for (int i = tid; i < 4608; i += 256) {
        int o = i & 7, klin = i >> 3;
        int ic = klin & 63, kxy = klin >> 6;
        int ky = kxy / 3, kx = kxy - ky * 3;
        swT[i] = w2[(size_t)(oc0 + o) * 576 + ic * 9 + ky * 3 + kx];
    }
    __syncthreads();

    int ty = tid >> 5, xc = tid & 31;
    unsigned long long acc0 = 0ULL, acc1 = 0ULL, acc2 = 0ULL, acc3 = 0ULL;

#pragma unroll
    for (int kxy = 0; kxy < 9; kxy++) {
        int ky = kxy / 3, kx = kxy - ky * 3;
        const float* tr = tile + (ty + ky) * 34 + (xc + kx);
        const unsigned long long* wp =
            (const unsigned long long*)(swT + kxy * 512);
#pragma unroll 8
        for (int ic = 0; ic < 64; ic++) {       // ic innermost: k = (ky,kx,ic)
            float v = tr[ic * 340];
            unsigned long long vv;
            asm("mov.b64 %0, {%1, %1};" : "=l"(vv) : "r"(__float_as_uint(v)));
            unsigned long long w01 = wp[ic * 4];
            unsigned long long w23 = wp[ic * 4 + 1];
            unsigned long long w45 = wp[ic * 4 + 2];
            unsigned long long w67 = wp[ic * 4 + 3];
            FMA2(acc0, vv, w01, acc0);
            FMA2(acc1, vv, w23, acc1);
            FMA2(acc2, vv, w45, acc2);
            FMA2(acc3, vv, w67, acc3);
        }
    }

    float acc[8];
    {
        unsigned int lo, hi;
        asm("mov.b64 {%0,%1}, %2;" : "=r"(lo), "=r"(hi) : "l"(acc0));
        acc[0] = __uint_as_float(lo); acc[1] = __uint_as_float(hi);
        asm("mov.b64 {%0,%1}, %2;" : "=r"(lo), "=r"(hi) : "l"(acc1));
        acc[2] = __uint_as_float(lo); acc[3] = __uint_as_float(hi);
        asm("mov.b64 {%0,%1}, %2;" : "=r"(lo), "=r"(hi) : "l"(acc2));
        acc[4] = __uint_as_float(lo); acc[5] = __uint_as_float(hi);
        asm("mov.b64 {%0,%1}, %2;" : "=r"(lo), "=r"(hi) : "l"(acc3));
        acc[6] = __uint_as_float(lo); acc[7] = __uint_as_float(hi);
    }

    int y = r0 + ty;
#pragma unroll
    for (int o = 0; o < 8; o++) {
        int oc = oc0 + o;
        float cur = __fadd_rn(acc[o], __ldg(&b2[oc]));
        size_t mi = ((size_t)(b * 128 + oc)) * 1024 + (size_t)y * 32 + xc;
        float m = g_mem2[mi];
        float reset = (m > 1.0f) ? 1.0f : 0.0f;
        m = __fsub_rn(__fadd_rn(__fmul_rn(0.95f, m), cur), reset);
        g_mem2[mi] = m;
        sspk[(o * 8 + ty) * 32 + xc] = (m > 1.0f) ? 1.f : 0.f;
    }
    __syncthreads();

    for (int j = tid; j < 512; j += 256) {
        int o = j >> 6, ph = (j >> 4) & 3, pw = j & 15;
        const float* sb2 = sspk + (o * 8 + ph * 2) * 32 + pw * 2;
        float s = fmaxf(fmaxf(sb2[0], sb2[1]), fmaxf(sb2[32], sb2[33]));
        g_p2[(size_t)b * 32768 + (oc0 + o) * 256 + (rowg * 4 + ph) * 16 + pw] = s;
    }
}

// ---------------------------------------------------------------------------
// Compact active spike indices per batch (ascending k). 1 block per b.
// ---------------------------------------------------------------------------
__global__ __launch_bounds__(1024) void compact_p2() {
    __shared__ int wsum[32];
    __shared__ int base;
    int b = blockIdx.x;
    int tid = threadIdx.x, lane = tid & 31, wid = tid >> 5;
    if (tid == 0) base = 0;
    __syncthreads();
    for (int c = 0; c < 32; c++) {
        int k = c * 1024 + tid;
        int flag = (g_p2[(size_t)b * 32768 + k] != 0.f);
        unsigned mask = __ballot_sync(0xffffffffu, flag);
        int my = __popc(mask & ((1u << lane) - 1));
        if (lane == 0) wsum[wid] = __popc(mask);
        __syncthreads();
        if (tid < 32) {
            int v = wsum[tid];
#pragma unroll
            for (int s = 1; s < 32; s <<= 1) {
                int u = __shfl_up_sync(0xffffffffu, v, s);
                if (lane >= s) v += u;
            }
            wsum[tid] = v;
        }
        __syncthreads();
        int prev = base + (wid ? wsum[wid - 1] : 0);
        if (flag) g_idx[(size_t)b * 32768 + prev + my] = k;
        int tot = wsum[31];
        __syncthreads();
        if (tid == 0) base += tot;
        __syncthreads();
    }
    if (threadIdx.x == 0) g_cnt[b] = base;
}

// ---------------------------------------------------------------------------
// fc1 (32768 -> 1024, M=16) + LIF3, sparse bit-exact gather version.
// grid 128 blocks x 128 threads; warp = (b, 32-o tile), lane = o.
// Chain: acc = fadd(acc, w1T[k][o]) over active k ascending -> bit-identical
// to dense fma chain (fma with spike 0 is exact identity, spike 1 is fadd).
// ---------------------------------------------------------------------------
__global__ __launch_bounds__(128) void fc1_k(const float* __restrict__ b1)
{
    int wid = threadIdx.x >> 5, lane = threadIdx.x & 31;
    int otile = blockIdx.x & 31;
    int b = (blockIdx.x >> 5) * 4 + wid;
    int o = otile * 32 + lane;

    const int n = g_cnt[b];
    const int* idx = g_idx + (size_t)b * 32768;
    const float* wt = g_w1T + o;

    float acc = 0.f;
    int i = 0;
    for (; i + 16 <= n; i += 16) {
        int ks[16];
#pragma unroll
        for (int j = 0; j < 16; j++) ks[j] = __ldg(idx + i + j);
        float ws[16];
#pragma unroll
        for (int j = 0; j < 16; j++) ws[j] = __ldg(wt + (size_t)ks[j] * 1024);
#pragma unroll
        for (int j = 0; j < 16; j++) acc = __fadd_rn(acc, ws[j]);
    }
    for (; i < n; i++)
        acc = __fadd_rn(acc, __ldg(wt + (size_t)__ldg(idx + i) * 1024));

    float cur = __fadd_rn(acc, b1[o]);
    size_t mi = (size_t)b * 1024 + o;
    float m = g_mem3[mi];
    float reset = (m > 1.0f) ? 1.0f : 0.0f;
    m = __fsub_rn(__fadd_rn(__fmul_rn(0.95f, m), cur), reset);
    g_mem3[mi] = m;
    g_s3[mi] = (m > 1.0f) ? 1.f : 0.f;
}

// ---------------------------------------------------------------------------
// fc2 (1024 -> 10) + LIF4, writes spikes to d_out [T,B,10]
// ---------------------------------------------------------------------------
__global__ __launch_bounds__(256) void fc2_k(
    const float* __restrict__ w2, const float* __restrict__ b2,
    float* __restrict__ out, int t)
{
    extern __shared__ float ss[];   // [1024][17], ss[k*17+b]
    int tid = threadIdx.x;
    for (int i = tid; i < 16 * 1024; i += 256) {
        int bb = i >> 10, k = i & 1023;
        ss[k * 17 + bb] = g_s3[(size_t)bb * 1024 + k];
    }
    __syncthreads();
    if (tid < 160) {
        int b = tid / 10, o = tid - b * 10;
        const float* wr = w2 + o * 1024;
        float acc = 0.f;
#pragma unroll 8
        for (int k = 0; k < 1024; k++)
            acc = fmaf(ss[k * 17 + b], wr[k], acc);
        float cur = __fadd_rn(acc, b2[o]);
        size_t mi = (size_t)b * 10 + o;
        float m = g_mem4[mi];
        float reset = (m > 1.0f) ? 1.0f : 0.0f;
        m = __fsub_rn(__fadd_rn(__fmul_rn(0.95f, m), cur), reset);
        g_mem4[mi] = m;
        out[((size_t)t * BB + b) * 10 + o] = (m > 1.0f) ? 1.f : 0.f;
    }
}

extern "C" void kernel_launch(void* const* d_in, const int* in_sizes, int n_in,
                              void* d_out, int out_size)
{
    const float* x       = (const float*)d_in[0];
    const float* conv1_w = (const float*)d_in[1];
    const float* conv1_b = (const float*)d_in[2];
    const float* conv2_w = (const float*)d_in[3];
    const float* conv2_b = (const float*)d_in[4];
    const float* fc1_w   = (const float*)d_in[5];
    const float* fc1_b   = (const float*)d_in[6];
    const float* fc2_w   = (const float*)d_in[7];
    const float* fc2_b   = (const float*)d_in[8];
    float* out = (float*)d_out;

    const int conv2_smem = (21760 + 4608 + 2048) * 4;
    const int fc2_smem   = 1024 * 17 * 4;
    cudaFuncSetAttribute(conv2_k, cudaFuncAttributeMaxDynamicSharedMemorySize, conv2_smem);
    cudaFuncSetAttribute(fc2_k,   cudaFuncAttributeMaxDynamicSharedMemorySize, fc2_smem);

    zero_mems<<<2048, 256>>>();
    {
        dim3 g(32768 / 32, 1024 / 32);
        transpose_w1<<<g, dim3(32, 8)>>>(fc1_w);
    }

    for (int t = 0; t < TT; t++) {
        conv1_k<<<BB * 64, 1024>>>(x, conv1_w, conv1_b, t);
        conv2_k<<<1024, 256, conv2_smem>>>(conv2_w, conv2_b);
        compact_p2<<<BB, 1024>>>();
        fc1_k<<<128, 128>>>(fc1_b);
        fc2_k<<<1, 256, fc2_smem>>>(fc2_w, fc2_b, out, t);
    }
}

// round 17
// speedup vs baseline: 1.0018x; 1.0018x over previous
#include <cuda_runtime.h>

#define BB 16
#define TT 16

// Persistent state / intermediates (allocation-free scratch)
__device__ float g_mem1[BB * 64 * 64 * 64];
__device__ float g_mem2[BB * 128 * 32 * 32];
__device__ float g_mem3[BB * 1024];
__device__ float g_mem4[BB * 10];
__device__ float g_p1[BB * 64 * 32 * 32];   // pooled spikes layer1
__device__ float g_p2[BB * 32768];          // pooled spikes layer2 (c*256+h*16+w)
__device__ float g_s3[BB * 1024];           // spikes layer3
__device__ float g_w1T[32768 * 1024];       // fc1 weights transposed [k][o]
__device__ int   g_idx[BB * 32768];         // per-b compacted active k (ascending)
__device__ int   g_cnt[BB];

__global__ void zero_mems() {
    int i = blockIdx.x * blockDim.x + threadIdx.x;
    int stride = gridDim.x * blockDim.x;
    for (int j = i; j < BB * 64 * 64 * 64; j += stride) g_mem1[j] = 0.f;
    for (int j = i; j < BB * 128 * 32 * 32; j += stride) g_mem2[j] = 0.f;
    for (int j = i; j < BB * 1024; j += stride) g_mem3[j] = 0.f;
    for (int j = i; j < BB * 10; j += stride) g_mem4[j] = 0.f;
}

// w1 [1024][32768] -> g_w1T [32768][1024], once per call
__global__ void transpose_w1(const float* __restrict__ w) {
    __shared__ float t[32][33];
    int k0 = blockIdx.x * 32;   // k tile
    int o0 = blockIdx.y * 32;   // o tile
    int tx = threadIdx.x, ty = threadIdx.y;      // 32 x 8
#pragma unroll
    for (int dy = 0; dy < 32; dy += 8)
        t[ty + dy][tx] = w[(size_t)(o0 + ty + dy) * 32768 + k0 + tx];
    __syncthreads();
#pragma unroll
    for (int dy = 0; dy < 32; dy += 8)
        g_w1T[(size_t)(k0 + ty + dy) * 1024 + o0 + tx] = t[tx][ty + dy];
}

// ---------------------------------------------------------------------------
// conv1 (2->64, 3x3 SAME, 64x64) + LIF1 + 2x2 maxpool of spikes
// ---------------------------------------------------------------------------
__global__ __launch_bounds__(1024) void conv1_k(
    const float* __restrict__ x, const float* __restrict__ w,
    const float* __restrict__ bias, int t)
{
    __shared__ float sw[18];
    __shared__ float sb;
    int b = blockIdx.x >> 6, oc = blockIdx.x & 63;
    int tid = threadIdx.x;
    if (tid < 18) sw[tid] = w[oc * 18 + tid];
    if (tid == 0) sb = bias[oc];
    __syncthreads();

    int ph = tid >> 5, pw = tid & 31;
    int y0 = ph * 2, x0 = pw * 2;
    const float* xb = x + ((size_t)(b * TT + t)) * 2 * 4096;

    float patch[2][4][4];
#pragma unroll
    for (int ic = 0; ic < 2; ic++)
#pragma unroll
        for (int r = 0; r < 4; r++) {
            int iy = y0 - 1 + r;
#pragma unroll
            for (int c = 0; c < 4; c++) {
                int ix = x0 - 1 + c;
                patch[ic][r][c] = (iy >= 0 && iy < 64 && ix >= 0 && ix < 64)
                                  ? xb[ic * 4096 + iy * 64 + ix] : 0.f;
            }
        }

    float a00 = 0.f, a01 = 0.f, a10 = 0.f, a11 = 0.f;
#pragma unroll
    for (int ky = 0; ky < 3; ky++)
#pragma unroll
        for (int kx = 0; kx < 3; kx++)
#pragma unroll
            for (int ic = 0; ic < 2; ic++) {   // ic innermost: k = (ky,kx,ic)
                float wv = sw[ic * 9 + ky * 3 + kx];
                a00 = fmaf(patch[ic][ky][kx],         wv, a00);
                a01 = fmaf(patch[ic][ky][kx + 1],     wv, a01);
                a10 = fmaf(patch[ic][ky + 1][kx],     wv, a10);
                a11 = fmaf(patch[ic][ky + 1][kx + 1], wv, a11);
            }

    float accs[4] = {a00, a01, a10, a11};
    float smax = 0.f;
    size_t mb = ((size_t)(b * 64 + oc)) * 4096;
#pragma unroll
    for (int dy = 0; dy < 2; dy++)
#pragma unroll
        for (int dx = 0; dx < 2; dx++) {
            size_t mi = mb + (size_t)(y0 + dy) * 64 + (x0 + dx);
            float cur = __fadd_rn(accs[dy * 2 + dx], sb);
            float m = g_mem1[mi];
            float reset = (m > 1.0f) ? 1.0f : 0.0f;
            m = __fsub_rn(__fadd_rn(__fmul_rn(0.95f, m), cur), reset);
            g_mem1[mi] = m;
            if (m > 1.0f) smax = 1.f;
        }
    g_p1[((size_t)(b * 64 + oc)) * 1024 + ph * 32 + pw] = smax;
}

// ---------------------------------------------------------------------------
// conv2 (64->128, 3x3 SAME, 32x32) + LIF2 + pool, packed f32x2 FMA
// block = 256 threads = 8 rows x 32 cols, 8 ocs/thread (4 f32x2 accs).
// grid = b(16) x rowgroup(4) x ocgroup(16) = 1024 blocks.
// ---------------------------------------------------------------------------
#define FMA2(d, a, bb_, c) \
    asm("fma.rn.f32x2 %0, %1, %2, %3;" : "=l"(d) : "l"(a), "l"(bb_), "l"(c))

__global__ __launch_bounds__(256) void conv2_k(
    const float* __restrict__ w2, const float* __restrict__ b2)
{
    extern __shared__ float sm[];
    float* tile = sm;                      // [64][10][34] = 21760 floats
    float* swT  = sm + 21760;              // [9*64][8]    = 4608 floats
    float* sspk = sm + 21760 + 4608;       // [8][8][32]   = 2048 floats
    int blk = blockIdx.x;
    int ocg = blk & 15, rowg = (blk >> 4) & 3, b = blk >> 6;
    int oc0 = ocg * 8, r0 = rowg * 8;
    int tid = threadIdx.x;

    for (int i = tid; i < 21760; i += 256) {
        int ic = i / 340, rem = i - ic * 340;
        int r = rem / 34, c = rem - r * 34;
        int iy = r0 - 1 + r, ix = c - 1;
        tile[i] = (iy >= 0 && iy < 32 && ix >= 0 && ix < 32)
                  ? g_p1[((size_t)(b * 64 + ic)) * 1024 + iy * 32 + ix] : 0.f;
    }
    for (int i = tid; i < 4608; i += 256) {
        int o = i & 7, klin = i >> 3;
        int ic = klin & 63, kxy = klin >> 6;
        int ky = kxy / 3, kx = kxy - ky * 3;
        swT[i] = w2[(size_t)(oc0 + o) * 576 + ic * 9 + ky * 3 + kx];
    }
    __syncthreads();

    int ty = tid >> 5, xc = tid & 31;
    unsigned long long acc0 = 0ULL, acc1 = 0ULL, acc2 = 0ULL, acc3 = 0ULL;

#pragma unroll
    for (int kxy = 0; kxy < 9; kxy++) {
        int ky = kxy / 3, kx = kxy - ky * 3;
        const float* tr = tile + (ty + ky) * 34 + (xc + kx);
        const unsigned long long* wp =
            (const unsigned long long*)(swT + kxy * 512);
#pragma unroll 8
        for (int ic = 0; ic < 64; ic++) {       // ic innermost: k = (ky,kx,ic)
            float v = tr[ic * 340];
            unsigned long long vv;
            asm("mov.b64 %0, {%1, %1};" : "=l"(vv) : "r"(__float_as_uint(v)));
            unsigned long long w01 = wp[ic * 4];
            unsigned long long w23 = wp[ic * 4 + 1];
            unsigned long long w45 = wp[ic * 4 + 2];
            unsigned long long w67 = wp[ic * 4 + 3];
            FMA2(acc0, vv, w01, acc0);
            FMA2(acc1, vv, w23, acc1);
            FMA2(acc2, vv, w45, acc2);
            FMA2(acc3, vv, w67, acc3);
        }
    }

    float acc[8];
    {
        unsigned int lo, hi;
        asm("mov.b64 {%0,%1}, %2;" : "=r"(lo), "=r"(hi) : "l"(acc0));
        acc[0] = __uint_as_float(lo); acc[1] = __uint_as_float(hi);
        asm("mov.b64 {%0,%1}, %2;" : "=r"(lo), "=r"(hi) : "l"(acc1));
        acc[2] = __uint_as_float(lo); acc[3] = __uint_as_float(hi);
        asm("mov.b64 {%0,%1}, %2;" : "=r"(lo), "=r"(hi) : "l"(acc2));
        acc[4] = __uint_as_float(lo); acc[5] = __uint_as_float(hi);
        asm("mov.b64 {%0,%1}, %2;" : "=r"(lo), "=r"(hi) : "l"(acc3));
        acc[6] = __uint_as_float(lo); acc[7] = __uint_as_float(hi);
    }

    int y = r0 + ty;
#pragma unroll
    for (int o = 0; o < 8; o++) {
        int oc = oc0 + o;
        float cur = __fadd_rn(acc[o], __ldg(&b2[oc]));
        size_t mi = ((size_t)(b * 128 + oc)) * 1024 + (size_t)y * 32 + xc;
        float m = g_mem2[mi];
        float reset = (m > 1.0f) ? 1.0f : 0.0f;
        m = __fsub_rn(__fadd_rn(__fmul_rn(0.95f, m), cur), reset);
        g_mem2[mi] = m;
        sspk[(o * 8 + ty) * 32 + xc] = (m > 1.0f) ? 1.f : 0.f;
    }
    __syncthreads();

    for (int j = tid; j < 512; j += 256) {
        int o = j >> 6, ph = (j >> 4) & 3, pw = j & 15;
        const float* sb2 = sspk + (o * 8 + ph * 2) * 32 + pw * 2;
        float s = fmaxf(fmaxf(sb2[0], sb2[1]), fmaxf(sb2[32], sb2[33]));
        g_p2[(size_t)b * 32768 + (oc0 + o) * 256 + (rowg * 4 + ph) * 16 + pw] = s;
    }
}

// ---------------------------------------------------------------------------
// Compact active spike indices per batch (ascending k). 1 block per b.
// ---------------------------------------------------------------------------
__global__ __launch_bounds__(1024) void compact_p2() {
    __shared__ int wsum[32];
    __shared__ int base;
    int b = blockIdx.x;
    int tid = threadIdx.x, lane = tid & 31, wid = tid >> 5;
    if (tid == 0) base = 0;
    __syncthreads();
    for (int c = 0; c < 32; c++) {
        int k = c * 1024 + tid;
        int flag = (g_p2[(size_t)b * 32768 + k] != 0.f);
        unsigned mask = __ballot_sync(0xffffffffu, flag);
        int my = __popc(mask & ((1u << lane) - 1));
        if (lane == 0) wsum[wid] = __popc(mask);
        __syncthreads();
        if (tid < 32) {
            int v = wsum[tid];
#pragma unroll
            for (int s = 1; s < 32; s <<= 1) {
                int u = __shfl_up_sync(0xffffffffu, v, s);
                if (lane >= s) v += u;
            }
            wsum[tid] = v;
        }
        __syncthreads();
        int prev = base + (wid ? wsum[wid - 1] : 0);
        if (flag) g_idx[(size_t)b * 32768 + prev + my] = k;
        int tot = wsum[31];
        __syncthreads();
        if (tid == 0) base += tot;
        __syncthreads();
    }
    if (threadIdx.x == 0) g_cnt[b] = base;
}

// ---------------------------------------------------------------------------
// fc1 (32768 -> 1024, M=16) + LIF3, sparse bit-exact gather version.
// grid 128 blocks x 128 threads; warp = (b, 32-o tile), lane = o.
// Chain: acc = fadd(acc, w1T[k][o]) over active k ascending -> bit-identical
// to dense fma chain (fma with spike 0 is exact identity, spike 1 is fadd).
// ---------------------------------------------------------------------------
__global__ __launch_bounds__(128) void fc1_k(const float* __restrict__ b1)
{
    int wid = threadIdx.x >> 5, lane = threadIdx.x & 31;
    int otile = blockIdx.x & 31;
    int b = (blockIdx.x >> 5) * 4 + wid;
    int o = otile * 32 + lane;

    const int n = g_cnt[b];
    const int* idx = g_idx + (size_t)b * 32768;
    const float* wt = g_w1T + o;

    float acc = 0.f;
    int i = 0;
    for (; i + 16 <= n; i += 16) {
        int ks[16];
#pragma unroll
        for (int j = 0; j < 16; j++) ks[j] = __ldg(idx + i + j);
        float ws[16];
#pragma unroll
        for (int j = 0; j < 16; j++) ws[j] = __ldg(wt + (size_t)ks[j] * 1024);
#pragma unroll
        for (int j = 0; j < 16; j++) acc = __fadd_rn(acc, ws[j]);
    }
    for (; i < n; i++)
        acc = __fadd_rn(acc, __ldg(wt + (size_t)__ldg(idx + i) * 1024));

    float cur = __fadd_rn(acc, b1[o]);
    size_t mi = (size_t)b * 1024 + o;
    float m = g_mem3[mi];
    float reset = (m > 1.0f) ? 1.0f : 0.0f;
    m = __fsub_rn(__fadd_rn(__fmul_rn(0.95f, m), cur), reset);
    g_mem3[mi] = m;
    g_s3[mi] = (m > 1.0f) ? 1.f : 0.f;
}

// ---------------------------------------------------------------------------
// fc2 (1024 -> 10) + LIF4, writes spikes to d_out [T,B,10]
// ---------------------------------------------------------------------------
__global__ __launch_bounds__(256) void fc2_k(
    const float* __restrict__ w2, const float* __restrict__ b2,
    float* __restrict__ out, int t)
{
    extern __shared__ float ss[];   // [1024][17], ss[k*17+b]
    int tid = threadIdx.x;
    for (int i = tid; i < 16 * 1024; i += 256) {
        int bb = i >> 10, k = i & 1023;
        ss[k * 17 + bb] = g_s3[(size_t)bb * 1024 + k];
    }
    __syncthreads();
    if (tid < 160) {
        int b = tid / 10, o = tid - b * 10;
        const float* wr = w2 + o * 1024;
        float acc = 0.f;
#pragma unroll 8
        for (int k = 0; k < 1024; k++)
            acc = fmaf(ss[k * 17 + b], wr[k], acc);
        float cur = __fadd_rn(acc, b2[o]);
        size_t mi = (size_t)b * 10 + o;
        float m = g_mem4[mi];
        float reset = (m > 1.0f) ? 1.0f : 0.0f;
        m = __fsub_rn(__fadd_rn(__fmul_rn(0.95f, m), cur), reset);
        g_mem4[mi] = m;
        out[((size_t)t * BB + b) * 10 + o] = (m > 1.0f) ? 1.f : 0.f;
    }
}

extern "C" void kernel_launch(void* const* d_in, const int* in_sizes, int n_in,
                              void* d_out, int out_size)
{
    const float* x       = (const float*)d_in[0];
    const float* conv1_w = (const float*)d_in[1];
    const float* conv1_b = (const float*)d_in[2];
    const float* conv2_w = (const float*)d_in[3];
    const float* conv2_b = (const float*)d_in[4];
    const float* fc1_w   = (const float*)d_in[5];
    const float* fc1_b   = (const float*)d_in[6];
    const float* fc2_w   = (const float*)d_in[7];
    const float* fc2_b   = (const float*)d_in[8];
    float* out = (float*)d_out;

    const int conv2_smem = (21760 + 4608 + 2048) * 4;
    const int fc2_smem   = 1024 * 17 * 4;
    cudaFuncSetAttribute(conv2_k, cudaFuncAttributeMaxDynamicSharedMemorySize, conv2_smem);
    cudaFuncSetAttribute(fc2_k,   cudaFuncAttributeMaxDynamicSharedMemorySize, fc2_smem);

    zero_mems<<<2048, 256>>>();
    {
        dim3 g(32768 / 32, 1024 / 32);
        transpose_w1<<<g, dim3(32, 8)>>>(fc1_w);
    }

    for (int t = 0; t < TT; t++) {
        conv1_k<<<BB * 64, 1024>>>(x, conv1_w, conv1_b, t);
        conv2_k<<<1024, 256, conv2_smem>>>(conv2_w, conv2_b);
        compact_p2<<<BB, 1024>>>();
        fc1_k<<<128, 128>>>(fc1_b);
        fc2_k<<<1, 256, fc2_smem>>>(fc2_w, fc2_b, out, t);
    }
}